// round 5
// baseline (speedup 1.0000x reference)
#include <cuda_runtime.h>
#include <cuda_bf16.h>
#include <stdint.h>
#include <math.h>
#include <string.h>

#define BN 64
#define TT 32
#define HD 1024
#define LL 196

// ---------------- device scratch --------------------------------------------
__device__ float g_X1p[(size_t)2048 * 4096];     // permuted x@w_ih1^T + biases (fp32)
__device__ uint2 g_w0p[(size_t)4096 * 512];      // w_ih1 packed (hi,lo) pairs, gate-interleaved
__device__ uint2 g_w1p[(size_t)4096 * 512];      // w_hh1 packed
__device__ uint2 g_wip[(size_t)4096 * 1024];     // w_ih2 packed (K=2048)
__device__ uint2 g_w2p[(size_t)4096 * 512];      // w_hh2 packed
__device__ __nv_bfloat16 g_xhi[(size_t)2048 * 1024];
__device__ __nv_bfloat16 g_xlo[(size_t)2048 * 1024];
__device__ __nv_bfloat16 g_h1hi[2][BN * HD], g_h1lo[2][BN * HD];
__device__ __nv_bfloat16 g_h2hi[2][BN * HD], g_h2lo[2][BN * HD];
__device__ __nv_bfloat16 g_vahi[BN * HD], g_valo[BN * HD];
__device__ float g_h1f[BN * HD];
__device__ float g_c1[BN * HD], g_c2[BN * HD];
__device__ float g_alpha[BN * LL];
__device__ float g_bs1[4096], g_bs2[4096];       // permuted bias sums

__device__ __forceinline__ float sigf(float x) { return 1.0f / (1.0f + expf(-x)); }

__device__ __forceinline__ unsigned short bfbits(__nv_bfloat16 h) {
    unsigned short s; memcpy(&s, &h, 2); return s;
}

__device__ __forceinline__ void mma_bf16(float c[4],
    uint32_t a0, uint32_t a1, uint32_t a2, uint32_t a3,
    uint32_t b0, uint32_t b1)
{
    asm volatile(
        "mma.sync.aligned.m16n8k16.row.col.f32.bf16.bf16.f32 "
        "{%0,%1,%2,%3}, {%4,%5,%6,%7}, {%8,%9}, {%0,%1,%2,%3};"
        : "+f"(c[0]), "+f"(c[1]), "+f"(c[2]), "+f"(c[3])
        : "r"(a0), "r"(a1), "r"(a2), "r"(a3), "r"(b0), "r"(b1));
}

// ---------------- setup kernels ---------------------------------------------
__global__ void zero_state() {
    int i = blockIdx.x * blockDim.x + threadIdx.x;
    if (i < BN * HD) {
        __nv_bfloat16 z = __float2bfloat16(0.f);
        g_h1hi[0][i] = z; g_h1lo[0][i] = z; g_h1hi[1][i] = z; g_h1lo[1][i] = z;
        g_h2hi[0][i] = z; g_h2lo[0][i] = z; g_h2hi[1][i] = z; g_h2lo[1][i] = z;
        g_c1[i] = 0.f; g_c2[i] = 0.f;
    }
}

// convert weight (rows 4096 x Kw fp32) -> gate-interleaved packed (hi,lo) pairs
__global__ __launch_bounds__(256) void conv_w(const float* __restrict__ w,
                                              uint2* __restrict__ dst, int Kw) {
    int idx = blockIdx.x * blockDim.x + threadIdx.x;   // pair index
    int pairs_per_row = Kw >> 1;
    if (idx >= 4096 * pairs_per_row) return;
    int j  = idx / pairs_per_row;
    int kp = idx - j * pairs_per_row;
    int src = (j & 3) * 1024 + (j >> 2);               // gate-interleave perm
    float v0 = w[(size_t)src * Kw + 2 * kp];
    float v1 = w[(size_t)src * Kw + 2 * kp + 1];
    __nv_bfloat16 h0 = __float2bfloat16(v0);
    __nv_bfloat16 h1 = __float2bfloat16(v1);
    __nv_bfloat16 l0 = __float2bfloat16(v0 - __bfloat162float(h0));
    __nv_bfloat16 l1 = __float2bfloat16(v1 - __bfloat162float(h1));
    uint2 o;
    o.x = (uint32_t)bfbits(h0) | ((uint32_t)bfbits(h1) << 16);
    o.y = (uint32_t)bfbits(l0) | ((uint32_t)bfbits(l1) << 16);
    dst[idx] = o;
}

__global__ void bias_prep(const float* b_ih1, const float* b_hh1,
                          const float* b_ih2, const float* b_hh2) {
    int j = blockIdx.x * blockDim.x + threadIdx.x;
    if (j < 4096) {
        int src = (j & 3) * 1024 + (j >> 2);
        g_bs1[j] = b_ih1[src] + b_hh1[src];
        g_bs2[j] = b_ih2[src] + b_hh2[src];
    }
}

// gather emb rows by token, split to bf16 hi/lo
__global__ __launch_bounds__(256) void gather_conv(const int* __restrict__ inp,
                                                   const float* __restrict__ emb) {
    int idx = blockIdx.x * blockDim.x + threadIdx.x;   // 0 .. 2048*1024
    int row = idx >> 10;
    int k   = idx & 1023;
    int tok = inp[row];
    float v = emb[(size_t)tok * 1024 + k];
    __nv_bfloat16 h = __float2bfloat16(v);
    g_xhi[idx] = h;
    g_xlo[idx] = __float2bfloat16(v - __bfloat162float(h));
}

// ---------------- X1 GEMM (tensor): X1p = xb @ w_ih1'^T + bs1 ---------------
// grid (128 col-slabs, 32 row-tiles), block 128 (4 warps, each m16 x n32)
__global__ __launch_bounds__(128) void mma_x1() {
    const int lane = threadIdx.x & 31;
    const int warp = threadIdx.x >> 5;
    const int slab = blockIdx.x * 32;
    const int rbase = blockIdx.y * 64;
    const int r_lo = warp * 16 + (lane >> 2);
    const int qk = (lane & 3) * 2;
    const int qp = lane & 3;

    float c[4][4] = {};

    const __nv_bfloat16* Ahi = g_xhi + (size_t)(rbase + r_lo) * 1024;
    const __nv_bfloat16* Alo = g_xlo + (size_t)(rbase + r_lo) * 1024;

    for (int ks = 0; ks < 64; ks++) {
        uint32_t ah0 = *(const uint32_t*)(Ahi + ks * 16 + qk);
        uint32_t ah1 = *(const uint32_t*)(Ahi + 8 * 1024 + ks * 16 + qk);
        uint32_t ah2 = *(const uint32_t*)(Ahi + ks * 16 + qk + 8);
        uint32_t ah3 = *(const uint32_t*)(Ahi + 8 * 1024 + ks * 16 + qk + 8);
        uint32_t al0 = *(const uint32_t*)(Alo + ks * 16 + qk);
        uint32_t al1 = *(const uint32_t*)(Alo + 8 * 1024 + ks * 16 + qk);
        uint32_t al2 = *(const uint32_t*)(Alo + ks * 16 + qk + 8);
        uint32_t al3 = *(const uint32_t*)(Alo + 8 * 1024 + ks * 16 + qk + 8);
        #pragma unroll
        for (int tl = 0; tl < 4; tl++) {
            int j = slab + tl * 8 + (lane >> 2);
            uint2 B0 = g_w0p[(size_t)j * 512 + ks * 8 + qp];
            uint2 B1 = g_w0p[(size_t)j * 512 + ks * 8 + qp + 4];
            mma_bf16(c[tl], ah0, ah1, ah2, ah3, B0.x, B1.x);
            mma_bf16(c[tl], ah0, ah1, ah2, ah3, B0.y, B1.y);
            mma_bf16(c[tl], al0, al1, al2, al3, B0.x, B1.x);
        }
    }

    #pragma unroll
    for (int tl = 0; tl < 4; tl++) {
        int j0 = slab + tl * 8 + qk;
        float2 bs = *(const float2*)(g_bs1 + j0);
        int row0 = rbase + r_lo;
        *(float2*)(g_X1p + (size_t)row0 * 4096 + j0) =
            make_float2(c[tl][0] + bs.x, c[tl][1] + bs.y);
        *(float2*)(g_X1p + (size_t)(row0 + 8) * 4096 + j0) =
            make_float2(c[tl][2] + bs.x, c[tl][3] + bs.y);
    }
}

// ---------------- fused tensor-core LSTM cell -------------------------------
// grid 128 (col slabs of 32 gate-interleaved cols = 8 d's), block 128.
// mode 1: gates = X1p[t] + h1@w_hh1'  -> h1 (bf16 split) + h1f (fp32), c1
// mode 2: gates = va@wih2'[:1024] + h1@wih2'[1024:] + h2@w_hh2' + bs2
//                 -> h2 (bf16 split), c2, out[t]
__global__ __launch_bounds__(128) void mma_cell(
    int mode, int t,
    const __nv_bfloat16* __restrict__ a0hi, const __nv_bfloat16* __restrict__ a0lo,
    const __nv_bfloat16* __restrict__ a1hi, const __nv_bfloat16* __restrict__ a1lo,
    const __nv_bfloat16* __restrict__ a2hi, const __nv_bfloat16* __restrict__ a2lo,
    __nv_bfloat16* __restrict__ hout_hi, __nv_bfloat16* __restrict__ hout_lo,
    float* __restrict__ c_state, float* __restrict__ fout)
{
    const int lane = threadIdx.x & 31;
    const int warp = threadIdx.x >> 5;
    const int slab = blockIdx.x * 32;
    const int r_lo = warp * 16 + (lane >> 2);
    const int qk = (lane & 3) * 2;
    const int qp = lane & 3;

    float c[4][4] = {};

    const int nseg = (mode == 1) ? 1 : 3;
    const __nv_bfloat16* AHI[3] = {a0hi, a1hi, a2hi};
    const __nv_bfloat16* ALO[3] = {a0lo, a1lo, a2lo};
    const uint2* WP[3];
    int PITCH[3], KOFF[3];
    if (mode == 1) {
        WP[0] = g_w1p; PITCH[0] = 512; KOFF[0] = 0;
    } else {
        WP[0] = g_wip; PITCH[0] = 1024; KOFF[0] = 0;
        WP[1] = g_wip; PITCH[1] = 1024; KOFF[1] = 512;
        WP[2] = g_w2p; PITCH[2] = 512;  KOFF[2] = 0;
    }

    for (int s = 0; s < nseg; s++) {
        const __nv_bfloat16* Ahi = AHI[s] + (size_t)r_lo * 1024;
        const __nv_bfloat16* Alo = ALO[s] + (size_t)r_lo * 1024;
        const uint2* W = WP[s];
        const int pit = PITCH[s];
        const int ko  = KOFF[s];
        for (int ks = 0; ks < 64; ks++) {
            uint32_t ah0 = *(const uint32_t*)(Ahi + ks * 16 + qk);
            uint32_t ah1 = *(const uint32_t*)(Ahi + 8 * 1024 + ks * 16 + qk);
            uint32_t ah2 = *(const uint32_t*)(Ahi + ks * 16 + qk + 8);
            uint32_t ah3 = *(const uint32_t*)(Ahi + 8 * 1024 + ks * 16 + qk + 8);
            uint32_t al0 = *(const uint32_t*)(Alo + ks * 16 + qk);
            uint32_t al1 = *(const uint32_t*)(Alo + 8 * 1024 + ks * 16 + qk);
            uint32_t al2 = *(const uint32_t*)(Alo + ks * 16 + qk + 8);
            uint32_t al3 = *(const uint32_t*)(Alo + 8 * 1024 + ks * 16 + qk + 8);
            #pragma unroll
            for (int tl = 0; tl < 4; tl++) {
                int j = slab + tl * 8 + (lane >> 2);
                uint2 B0 = W[(size_t)j * pit + ko + ks * 8 + qp];
                uint2 B1 = W[(size_t)j * pit + ko + ks * 8 + qp + 4];
                mma_bf16(c[tl], ah0, ah1, ah2, ah3, B0.x, B1.x);
                mma_bf16(c[tl], ah0, ah1, ah2, ah3, B0.y, B1.y);
                mma_bf16(c[tl], al0, al1, al2, al3, B0.x, B1.x);
            }
        }
    }

    // epilogue: addend, lane-pair gate exchange, activation
    const bool has_if = ((lane & 1) == 0);   // (lane&3) in {0,2}: holds gates {i,f}
    const int d = (slab >> 2);               // d base for this slab

    #pragma unroll
    for (int tl = 0; tl < 4; tl++) {
        int j0 = slab + tl * 8 + qk;
        float x0, x1, x2, x3;
        if (mode == 1) {
            const float* x1p = g_X1p + (size_t)(t * 64 + r_lo) * 4096 + j0;
            float2 aL = *(const float2*)x1p;
            float2 aH = *(const float2*)(x1p + 8 * 4096);
            x0 = c[tl][0] + aL.x; x1 = c[tl][1] + aL.y;
            x2 = c[tl][2] + aH.x; x3 = c[tl][3] + aH.y;
        } else {
            float2 bs = *(const float2*)(g_bs2 + j0);
            x0 = c[tl][0] + bs.x; x1 = c[tl][1] + bs.y;
            x2 = c[tl][2] + bs.x; x3 = c[tl][3] + bs.y;
        }
        float y0 = __shfl_xor_sync(0xffffffffu, x0, 1);
        float y1 = __shfl_xor_sync(0xffffffffu, x1, 1);
        float y2 = __shfl_xor_sync(0xffffffffu, x2, 1);
        float y3 = __shfl_xor_sync(0xffffffffu, x3, 1);

        if (has_if) {
            int dd = d + tl * 2 + ((lane & 3) >> 1);   // lane&3==0 -> +0, ==2 -> +1
            #pragma unroll
            for (int rr = 0; rr < 2; rr++) {
                float iv = rr ? x2 : x0;
                float fv = rr ? x3 : x1;
                float gv = rr ? y2 : y0;
                float ov = rr ? y3 : y1;
                int n = r_lo + rr * 8;
                int idx = n * 1024 + dd;
                float ig = sigf(iv), fg = sigf(fv);
                float gg = tanhf(gv), og = sigf(ov);
                float cn = fg * c_state[idx] + ig * gg;
                c_state[idx] = cn;
                float hn = og * tanhf(cn);
                __nv_bfloat16 hh = __float2bfloat16(hn);
                hout_hi[idx] = hh;
                hout_lo[idx] = __float2bfloat16(hn - __bfloat162float(hh));
                if (mode == 1) fout[idx] = hn;                      // h1f for attention
                else fout[(size_t)(t * 64 + n) * 1024 + dd] = hn;   // output
            }
        }
    }
}

// ---------------- attention (fp32 SIMT, high parallelism) -------------------
__global__ __launch_bounds__(256) void attn_alpha(const float* __restrict__ img) {
    __shared__ float sh[1024];
    const int n = blockIdx.x;
    const int lbase = blockIdx.y * 28;
    {
        int i = threadIdx.x;
        *(float4*)&sh[i * 4] = *(const float4*)(g_h1f + (size_t)n * 1024 + i * 4);
    }
    __syncthreads();

    const int w = threadIdx.x >> 5;
    const int lane = threadIdx.x & 31;
    for (int l = lbase + w; l < lbase + 28; l += 8) {
        const float* f = img + ((size_t)n * LL + l) * 1024;
        float s = 0.f;
        #pragma unroll
        for (int i = 0; i < 8; i++) {
            int dd = i * 128 + lane * 4;
            float4 fv = *(const float4*)(f + dd);
            s += fv.x * sh[dd] + fv.y * sh[dd + 1] + fv.z * sh[dd + 2] + fv.w * sh[dd + 3];
        }
        #pragma unroll
        for (int off = 16; off; off >>= 1)
            s += __shfl_xor_sync(0xffffffffu, s, off);
        if (lane == 0) g_alpha[n * LL + l] = s;
    }
}

__global__ __launch_bounds__(256) void attn_vatt(const float* __restrict__ img) {
    __shared__ float sa[LL];
    const int n = blockIdx.x;
    const int d = blockIdx.y * 256 + threadIdx.x;
    if (threadIdx.x < LL) sa[threadIdx.x] = g_alpha[n * LL + threadIdx.x];
    __syncthreads();

    const float* f = img + (size_t)n * LL * 1024 + d;
    float s = 0.f;
    #pragma unroll 4
    for (int l = 0; l < LL; l++)
        s += sa[l] * f[(size_t)l * 1024];

    int idx = n * 1024 + d;
    __nv_bfloat16 h = __float2bfloat16(s);
    g_vahi[idx] = h;
    g_valo[idx] = __float2bfloat16(s - __bfloat162float(h));
}

// ---------------- launch -----------------------------------------------------
extern "C" void kernel_launch(void* const* d_in, const int* in_sizes, int n_in,
                              void* d_out, int out_size)
{
    const int*   inputs = (const int*)  d_in[0];
    const float* img    = (const float*)d_in[1];
    const float* emb    = (const float*)d_in[2];
    const float* w_ih1  = (const float*)d_in[3];
    const float* w_hh1  = (const float*)d_in[4];
    const float* b_ih1  = (const float*)d_in[5];
    const float* b_hh1  = (const float*)d_in[6];
    const float* w_ih2  = (const float*)d_in[7];
    const float* w_hh2  = (const float*)d_in[8];
    const float* b_ih2  = (const float*)d_in[9];
    const float* b_hh2  = (const float*)d_in[10];
    float* out = (float*)d_out;
    (void)in_sizes; (void)n_in; (void)out_size;

    static __nv_bfloat16 *h1hi[2], *h1lo[2], *h2hi[2], *h2lo[2], *vahi, *valo;
    static float *c1p, *c2p, *h1fp;
    static uint2 *w0p, *w1p, *wip, *w2p;
    static bool init = false;
    if (!init) {
        void* tmp;
        cudaGetSymbolAddress(&tmp, g_h1hi); h1hi[0] = (__nv_bfloat16*)tmp; h1hi[1] = h1hi[0] + BN * HD;
        cudaGetSymbolAddress(&tmp, g_h1lo); h1lo[0] = (__nv_bfloat16*)tmp; h1lo[1] = h1lo[0] + BN * HD;
        cudaGetSymbolAddress(&tmp, g_h2hi); h2hi[0] = (__nv_bfloat16*)tmp; h2hi[1] = h2hi[0] + BN * HD;
        cudaGetSymbolAddress(&tmp, g_h2lo); h2lo[0] = (__nv_bfloat16*)tmp; h2lo[1] = h2lo[0] + BN * HD;
        cudaGetSymbolAddress(&tmp, g_vahi); vahi = (__nv_bfloat16*)tmp;
        cudaGetSymbolAddress(&tmp, g_valo); valo = (__nv_bfloat16*)tmp;
        cudaGetSymbolAddress(&tmp, g_c1);   c1p = (float*)tmp;
        cudaGetSymbolAddress(&tmp, g_c2);   c2p = (float*)tmp;
        cudaGetSymbolAddress(&tmp, g_h1f);  h1fp = (float*)tmp;
        cudaGetSymbolAddress(&tmp, g_w0p);  w0p = (uint2*)tmp;
        cudaGetSymbolAddress(&tmp, g_w1p);  w1p = (uint2*)tmp;
        cudaGetSymbolAddress(&tmp, g_wip);  wip = (uint2*)tmp;
        cudaGetSymbolAddress(&tmp, g_w2p);  w2p = (uint2*)tmp;
        init = true;
    }

    zero_state<<<256, 256>>>();
    conv_w<<<(4096 * 512 + 255) / 256, 256>>>(w_ih1, w0p, 1024);
    conv_w<<<(4096 * 512 + 255) / 256, 256>>>(w_hh1, w1p, 1024);
    conv_w<<<(4096 * 1024 + 255) / 256, 256>>>(w_ih2, wip, 2048);
    conv_w<<<(4096 * 512 + 255) / 256, 256>>>(w_hh2, w2p, 1024);
    bias_prep<<<16, 256>>>(b_ih1, b_hh1, b_ih2, b_hh2);
    gather_conv<<<(2048 * 1024) / 256, 256>>>(inputs, emb);
    mma_x1<<<dim3(128, 32), 128>>>();

    for (int t = 0; t < TT; t++) {
        const int p = t & 1;
        // cell 1: reads h1[p] bf16, writes h1[1-p] bf16 + h1f fp32, c1
        mma_cell<<<128, 128>>>(1, t,
            h1hi[p], h1lo[p], nullptr, nullptr, nullptr, nullptr,
            h1hi[1 - p], h1lo[1 - p], c1p, h1fp);
        attn_alpha<<<dim3(64, 7), 256>>>(img);
        attn_vatt<<<dim3(64, 4), 256>>>(img);
        // cell 2: reads va, h1[1-p], h2[p]; writes h2[1-p], c2, out[t]
        mma_cell<<<128, 128>>>(2, t,
            vahi, valo, h1hi[1 - p], h1lo[1 - p], h2hi[p], h2lo[p],
            h2hi[1 - p], h2lo[1 - p], c2p, out);
    }
}

// round 6
// speedup vs baseline: 2.7927x; 2.7927x over previous
#include <cuda_runtime.h>
#include <cuda_bf16.h>
#include <stdint.h>
#include <math.h>
#include <string.h>

#define BN 64
#define TT 32
#define HD 1024
#define LL 196

// ---------------- device scratch --------------------------------------------
__device__ float g_X1p[(size_t)2048 * 4096];     // permuted x@w_ih1^T + biases (fp32)
__device__ uint2 g_w0p[(size_t)4096 * 512];      // w_ih1 packed (hi,lo) pairs, gate-interleaved
__device__ uint2 g_w1p[(size_t)4096 * 512];      // w_hh1 packed
__device__ uint2 g_wip[(size_t)4096 * 1024];     // w_ih2 packed (K=2048)
__device__ uint2 g_w2p[(size_t)4096 * 512];      // w_hh2 packed
__device__ __nv_bfloat16 g_xhi[(size_t)2048 * 1024];
__device__ __nv_bfloat16 g_xlo[(size_t)2048 * 1024];
__device__ __nv_bfloat16 g_h1hi[2][BN * HD], g_h1lo[2][BN * HD];
__device__ __nv_bfloat16 g_h2hi[2][BN * HD], g_h2lo[2][BN * HD];
__device__ __nv_bfloat16 g_vahi[BN * HD], g_valo[BN * HD];
__device__ float g_h1f[BN * HD];
__device__ float g_c1[BN * HD], g_c2[BN * HD];
__device__ float g_alpha[BN * LL];
__device__ float g_bs1[4096], g_bs2[4096];       // permuted bias sums

__device__ __forceinline__ float sigf(float x) { return 1.0f / (1.0f + expf(-x)); }

__device__ __forceinline__ unsigned short bfbits(__nv_bfloat16 h) {
    unsigned short s; memcpy(&s, &h, 2); return s;
}

__device__ __forceinline__ void mma_bf16(float c[4],
    uint32_t a0, uint32_t a1, uint32_t a2, uint32_t a3,
    uint32_t b0, uint32_t b1)
{
    asm volatile(
        "mma.sync.aligned.m16n8k16.row.col.f32.bf16.bf16.f32 "
        "{%0,%1,%2,%3}, {%4,%5,%6,%7}, {%8,%9}, {%0,%1,%2,%3};"
        : "+f"(c[0]), "+f"(c[1]), "+f"(c[2]), "+f"(c[3])
        : "r"(a0), "r"(a1), "r"(a2), "r"(a3), "r"(b0), "r"(b1));
}

// ---------------- setup kernels ---------------------------------------------
__global__ void zero_state() {
    int i = blockIdx.x * blockDim.x + threadIdx.x;
    if (i < BN * HD) {
        __nv_bfloat16 z = __float2bfloat16(0.f);
        g_h1hi[0][i] = z; g_h1lo[0][i] = z; g_h1hi[1][i] = z; g_h1lo[1][i] = z;
        g_h2hi[0][i] = z; g_h2lo[0][i] = z; g_h2hi[1][i] = z; g_h2lo[1][i] = z;
        g_c1[i] = 0.f; g_c2[i] = 0.f;
    }
}

// convert weight (rows 4096 x Kw fp32) -> gate-interleaved packed (hi,lo) pairs
__global__ __launch_bounds__(256) void conv_w(const float* __restrict__ w,
                                              uint2* __restrict__ dst, int Kw) {
    int idx = blockIdx.x * blockDim.x + threadIdx.x;   // pair index
    int pairs_per_row = Kw >> 1;
    if (idx >= 4096 * pairs_per_row) return;
    int j  = idx / pairs_per_row;
    int kp = idx - j * pairs_per_row;
    int src = (j & 3) * 1024 + (j >> 2);               // gate-interleave perm
    float v0 = w[(size_t)src * Kw + 2 * kp];
    float v1 = w[(size_t)src * Kw + 2 * kp + 1];
    __nv_bfloat16 h0 = __float2bfloat16(v0);
    __nv_bfloat16 h1 = __float2bfloat16(v1);
    __nv_bfloat16 l0 = __float2bfloat16(v0 - __bfloat162float(h0));
    __nv_bfloat16 l1 = __float2bfloat16(v1 - __bfloat162float(h1));
    uint2 o;
    o.x = (uint32_t)bfbits(h0) | ((uint32_t)bfbits(h1) << 16);
    o.y = (uint32_t)bfbits(l0) | ((uint32_t)bfbits(l1) << 16);
    dst[idx] = o;
}

__global__ void bias_prep(const float* b_ih1, const float* b_hh1,
                          const float* b_ih2, const float* b_hh2) {
    int j = blockIdx.x * blockDim.x + threadIdx.x;
    if (j < 4096) {
        int src = (j & 3) * 1024 + (j >> 2);
        g_bs1[j] = b_ih1[src] + b_hh1[src];
        g_bs2[j] = b_ih2[src] + b_hh2[src];
    }
}

// gather emb rows by token, split to bf16 hi/lo
__global__ __launch_bounds__(256) void gather_conv(const int* __restrict__ inp,
                                                   const float* __restrict__ emb) {
    int idx = blockIdx.x * blockDim.x + threadIdx.x;   // 0 .. 2048*1024
    int row = idx >> 10;
    int k   = idx & 1023;
    int tok = inp[row];
    float v = emb[(size_t)tok * 1024 + k];
    __nv_bfloat16 h = __float2bfloat16(v);
    g_xhi[idx] = h;
    g_xlo[idx] = __float2bfloat16(v - __bfloat162float(h));
}

// ---------------- X1 GEMM (tensor): X1p = xb @ w_ih1'^T + bs1 ---------------
// grid (128 col-slabs, 32 row-tiles), block 128 (4 warps, each m16 x n32)
__global__ __launch_bounds__(128) void mma_x1() {
    const int lane = threadIdx.x & 31;
    const int warp = threadIdx.x >> 5;
    const int slab = blockIdx.x * 32;
    const int rbase = blockIdx.y * 64;
    const int r_lo = warp * 16 + (lane >> 2);
    const int qk = (lane & 3) * 2;
    const int qp = lane & 3;

    float c[4][4] = {};

    const __nv_bfloat16* Ahi = g_xhi + (size_t)(rbase + r_lo) * 1024;
    const __nv_bfloat16* Alo = g_xlo + (size_t)(rbase + r_lo) * 1024;

    for (int ks = 0; ks < 64; ks++) {
        uint32_t ah0 = *(const uint32_t*)(Ahi + ks * 16 + qk);
        uint32_t ah1 = *(const uint32_t*)(Ahi + 8 * 1024 + ks * 16 + qk);
        uint32_t ah2 = *(const uint32_t*)(Ahi + ks * 16 + qk + 8);
        uint32_t ah3 = *(const uint32_t*)(Ahi + 8 * 1024 + ks * 16 + qk + 8);
        uint32_t al0 = *(const uint32_t*)(Alo + ks * 16 + qk);
        uint32_t al1 = *(const uint32_t*)(Alo + 8 * 1024 + ks * 16 + qk);
        uint32_t al2 = *(const uint32_t*)(Alo + ks * 16 + qk + 8);
        uint32_t al3 = *(const uint32_t*)(Alo + 8 * 1024 + ks * 16 + qk + 8);
        #pragma unroll
        for (int tl = 0; tl < 4; tl++) {
            int j = slab + tl * 8 + (lane >> 2);
            uint2 B0 = g_w0p[(size_t)j * 512 + ks * 8 + qp];
            uint2 B1 = g_w0p[(size_t)j * 512 + ks * 8 + qp + 4];
            mma_bf16(c[tl], ah0, ah1, ah2, ah3, B0.x, B1.x);
            mma_bf16(c[tl], ah0, ah1, ah2, ah3, B0.y, B1.y);
            mma_bf16(c[tl], al0, al1, al2, al3, B0.x, B1.x);
        }
    }

    #pragma unroll
    for (int tl = 0; tl < 4; tl++) {
        int j0 = slab + tl * 8 + qk;
        float2 bs = *(const float2*)(g_bs1 + j0);
        int row0 = rbase + r_lo;
        *(float2*)(g_X1p + (size_t)row0 * 4096 + j0) =
            make_float2(c[tl][0] + bs.x, c[tl][1] + bs.y);
        *(float2*)(g_X1p + (size_t)(row0 + 8) * 4096 + j0) =
            make_float2(c[tl][2] + bs.x, c[tl][3] + bs.y);
    }
}

// ---------------- fused tensor-core LSTM cell, split-K x4 -------------------
// grid 128 (col slabs of 32 gate-interleaved cols = 8 d's), block 512 (16 warps):
// warp = kslice(0..3) * 4 + wr(0..3).  wr -> m16 rows; kslice -> K/4 slice.
// fp32 reduce through smem, epilogue on warps 0-3 (full LSTM activation).
__global__ __launch_bounds__(512) void mma_cell(
    int mode, int t,
    const __nv_bfloat16* __restrict__ a0hi, const __nv_bfloat16* __restrict__ a0lo,
    const __nv_bfloat16* __restrict__ a1hi, const __nv_bfloat16* __restrict__ a1lo,
    const __nv_bfloat16* __restrict__ a2hi, const __nv_bfloat16* __restrict__ a2lo,
    __nv_bfloat16* __restrict__ hout_hi, __nv_bfloat16* __restrict__ hout_lo,
    float* __restrict__ c_state, float* __restrict__ fout)
{
    __shared__ float red[4][4][32][17];     // [kslice][wr][lane][16 accs] padded

    const int lane   = threadIdx.x & 31;
    const int warp   = threadIdx.x >> 5;
    const int kslice = warp >> 2;
    const int wr     = warp & 3;
    const int slab   = blockIdx.x * 32;
    const int r_lo   = wr * 16 + (lane >> 2);
    const int qk = (lane & 3) * 2;
    const int qp = lane & 3;

    float c[4][4] = {};

    const int nseg = (mode == 1) ? 1 : 3;
    const __nv_bfloat16* AHI[3] = {a0hi, a1hi, a2hi};
    const __nv_bfloat16* ALO[3] = {a0lo, a1lo, a2lo};
    const uint2* WP[3];
    int PITCH[3], KOFF[3];
    if (mode == 1) {
        WP[0] = g_w1p; PITCH[0] = 512; KOFF[0] = 0;
    } else {
        WP[0] = g_wip; PITCH[0] = 1024; KOFF[0] = 0;
        WP[1] = g_wip; PITCH[1] = 1024; KOFF[1] = 512;
        WP[2] = g_w2p; PITCH[2] = 512;  KOFF[2] = 0;
    }

    for (int s = 0; s < nseg; s++) {
        const __nv_bfloat16* Ahi = AHI[s] + (size_t)r_lo * 1024;
        const __nv_bfloat16* Alo = ALO[s] + (size_t)r_lo * 1024;
        const uint2* W = WP[s];
        const int pit = PITCH[s];
        const int ko  = KOFF[s];
        #pragma unroll 4
        for (int it = 0; it < 16; it++) {
            const int ks = kslice * 16 + it;      // this warp's K slice
            uint32_t ah0 = *(const uint32_t*)(Ahi + ks * 16 + qk);
            uint32_t ah1 = *(const uint32_t*)(Ahi + 8 * 1024 + ks * 16 + qk);
            uint32_t ah2 = *(const uint32_t*)(Ahi + ks * 16 + qk + 8);
            uint32_t ah3 = *(const uint32_t*)(Ahi + 8 * 1024 + ks * 16 + qk + 8);
            uint32_t al0 = *(const uint32_t*)(Alo + ks * 16 + qk);
            uint32_t al1 = *(const uint32_t*)(Alo + 8 * 1024 + ks * 16 + qk);
            uint32_t al2 = *(const uint32_t*)(Alo + ks * 16 + qk + 8);
            uint32_t al3 = *(const uint32_t*)(Alo + 8 * 1024 + ks * 16 + qk + 8);
            #pragma unroll
            for (int tl = 0; tl < 4; tl++) {
                int j = slab + tl * 8 + (lane >> 2);
                uint2 B0 = W[(size_t)j * pit + ko + ks * 8 + qp];
                uint2 B1 = W[(size_t)j * pit + ko + ks * 8 + qp + 4];
                mma_bf16(c[tl], ah0, ah1, ah2, ah3, B0.x, B1.x);
                mma_bf16(c[tl], ah0, ah1, ah2, ah3, B0.y, B1.y);
                mma_bf16(c[tl], al0, al1, al2, al3, B0.x, B1.x);
            }
        }
    }

    // write partials to smem
    #pragma unroll
    for (int tl = 0; tl < 4; tl++)
        #pragma unroll
        for (int i = 0; i < 4; i++)
            red[kslice][wr][lane][tl * 4 + i] = c[tl][i];
    __syncthreads();

    if (warp >= 4) return;   // epilogue on warps 0-3 (kslice==0, wr==warp)

    // reduce 4 k-slices
    #pragma unroll
    for (int tl = 0; tl < 4; tl++)
        #pragma unroll
        for (int i = 0; i < 4; i++)
            c[tl][i] = red[0][wr][lane][tl * 4 + i] + red[1][wr][lane][tl * 4 + i]
                     + red[2][wr][lane][tl * 4 + i] + red[3][wr][lane][tl * 4 + i];

    // epilogue: addend, lane-pair gate exchange, activation
    const bool has_if = ((lane & 1) == 0);   // (lane&3) in {0,2}: holds gates {i,f}
    const int d = (slab >> 2);               // d base for this slab

    #pragma unroll
    for (int tl = 0; tl < 4; tl++) {
        int j0 = slab + tl * 8 + qk;
        float x0, x1, x2, x3;
        if (mode == 1) {
            const float* x1p = g_X1p + (size_t)(t * 64 + r_lo) * 4096 + j0;
            float2 aL = *(const float2*)x1p;
            float2 aH = *(const float2*)(x1p + 8 * 4096);
            x0 = c[tl][0] + aL.x; x1 = c[tl][1] + aL.y;
            x2 = c[tl][2] + aH.x; x3 = c[tl][3] + aH.y;
        } else {
            float2 bs = *(const float2*)(g_bs2 + j0);
            x0 = c[tl][0] + bs.x; x1 = c[tl][1] + bs.y;
            x2 = c[tl][2] + bs.x; x3 = c[tl][3] + bs.y;
        }
        float y0 = __shfl_xor_sync(0xffffffffu, x0, 1);
        float y1 = __shfl_xor_sync(0xffffffffu, x1, 1);
        float y2 = __shfl_xor_sync(0xffffffffu, x2, 1);
        float y3 = __shfl_xor_sync(0xffffffffu, x3, 1);

        if (has_if) {
            int dd = d + tl * 2 + ((lane & 3) >> 1);   // lane&3==0 -> +0, ==2 -> +1
            #pragma unroll
            for (int rr = 0; rr < 2; rr++) {
                float iv = rr ? x2 : x0;
                float fv = rr ? x3 : x1;
                float gv = rr ? y2 : y0;
                float ov = rr ? y3 : y1;
                int n = r_lo + rr * 8;
                int idx = n * 1024 + dd;
                float ig = sigf(iv), fg = sigf(fv);
                float gg = tanhf(gv), og = sigf(ov);
                float cn = fg * c_state[idx] + ig * gg;
                c_state[idx] = cn;
                float hn = og * tanhf(cn);
                __nv_bfloat16 hh = __float2bfloat16(hn);
                hout_hi[idx] = hh;
                hout_lo[idx] = __float2bfloat16(hn - __bfloat162float(hh));
                if (mode == 1) fout[idx] = hn;                      // h1f for attention
                else fout[(size_t)(t * 64 + n) * 1024 + dd] = hn;   // output
            }
        }
    }
}

// ---------------- attention (fp32 SIMT, high parallelism) -------------------
__global__ __launch_bounds__(256) void attn_alpha(const float* __restrict__ img) {
    __shared__ float sh[1024];
    const int n = blockIdx.x;
    const int lbase = blockIdx.y * 28;
    {
        int i = threadIdx.x;
        *(float4*)&sh[i * 4] = *(const float4*)(g_h1f + (size_t)n * 1024 + i * 4);
    }
    __syncthreads();

    const int w = threadIdx.x >> 5;
    const int lane = threadIdx.x & 31;
    for (int l = lbase + w; l < lbase + 28; l += 8) {
        const float* f = img + ((size_t)n * LL + l) * 1024;
        float s = 0.f;
        #pragma unroll
        for (int i = 0; i < 8; i++) {
            int dd = i * 128 + lane * 4;
            float4 fv = *(const float4*)(f + dd);
            s += fv.x * sh[dd] + fv.y * sh[dd + 1] + fv.z * sh[dd + 2] + fv.w * sh[dd + 3];
        }
        #pragma unroll
        for (int off = 16; off; off >>= 1)
            s += __shfl_xor_sync(0xffffffffu, s, off);
        if (lane == 0) g_alpha[n * LL + l] = s;
    }
}

__global__ __launch_bounds__(256) void attn_vatt(const float* __restrict__ img) {
    __shared__ float sa[LL];
    const int n = blockIdx.x;
    const int d = blockIdx.y * 256 + threadIdx.x;
    if (threadIdx.x < LL) sa[threadIdx.x] = g_alpha[n * LL + threadIdx.x];
    __syncthreads();

    const float* f = img + (size_t)n * LL * 1024 + d;
    float s = 0.f;
    #pragma unroll 4
    for (int l = 0; l < LL; l++)
        s += sa[l] * f[(size_t)l * 1024];

    int idx = n * 1024 + d;
    __nv_bfloat16 h = __float2bfloat16(s);
    g_vahi[idx] = h;
    g_valo[idx] = __float2bfloat16(s - __bfloat162float(h));
}

// ---------------- launch -----------------------------------------------------
extern "C" void kernel_launch(void* const* d_in, const int* in_sizes, int n_in,
                              void* d_out, int out_size)
{
    const int*   inputs = (const int*)  d_in[0];
    const float* img    = (const float*)d_in[1];
    const float* emb    = (const float*)d_in[2];
    const float* w_ih1  = (const float*)d_in[3];
    const float* w_hh1  = (const float*)d_in[4];
    const float* b_ih1  = (const float*)d_in[5];
    const float* b_hh1  = (const float*)d_in[6];
    const float* w_ih2  = (const float*)d_in[7];
    const float* w_hh2  = (const float*)d_in[8];
    const float* b_ih2  = (const float*)d_in[9];
    const float* b_hh2  = (const float*)d_in[10];
    float* out = (float*)d_out;
    (void)in_sizes; (void)n_in; (void)out_size;

    static __nv_bfloat16 *h1hi[2], *h1lo[2], *h2hi[2], *h2lo[2], *vahi, *valo;
    static float *c1p, *c2p, *h1fp;
    static uint2 *w0p, *w1p, *wip, *w2p;
    static bool init = false;
    if (!init) {
        void* tmp;
        cudaGetSymbolAddress(&tmp, g_h1hi); h1hi[0] = (__nv_bfloat16*)tmp; h1hi[1] = h1hi[0] + BN * HD;
        cudaGetSymbolAddress(&tmp, g_h1lo); h1lo[0] = (__nv_bfloat16*)tmp; h1lo[1] = h1lo[0] + BN * HD;
        cudaGetSymbolAddress(&tmp, g_h2hi); h2hi[0] = (__nv_bfloat16*)tmp; h2hi[1] = h2hi[0] + BN * HD;
        cudaGetSymbolAddress(&tmp, g_h2lo); h2lo[0] = (__nv_bfloat16*)tmp; h2lo[1] = h2lo[0] + BN * HD;
        cudaGetSymbolAddress(&tmp, g_vahi); vahi = (__nv_bfloat16*)tmp;
        cudaGetSymbolAddress(&tmp, g_valo); valo = (__nv_bfloat16*)tmp;
        cudaGetSymbolAddress(&tmp, g_c1);   c1p = (float*)tmp;
        cudaGetSymbolAddress(&tmp, g_c2);   c2p = (float*)tmp;
        cudaGetSymbolAddress(&tmp, g_h1f);  h1fp = (float*)tmp;
        cudaGetSymbolAddress(&tmp, g_w0p);  w0p = (uint2*)tmp;
        cudaGetSymbolAddress(&tmp, g_w1p);  w1p = (uint2*)tmp;
        cudaGetSymbolAddress(&tmp, g_wip);  wip = (uint2*)tmp;
        cudaGetSymbolAddress(&tmp, g_w2p);  w2p = (uint2*)tmp;
        init = true;
    }

    zero_state<<<256, 256>>>();
    conv_w<<<(4096 * 512 + 255) / 256, 256>>>(w_ih1, w0p, 1024);
    conv_w<<<(4096 * 512 + 255) / 256, 256>>>(w_hh1, w1p, 1024);
    conv_w<<<(4096 * 1024 + 255) / 256, 256>>>(w_ih2, wip, 2048);
    conv_w<<<(4096 * 512 + 255) / 256, 256>>>(w_hh2, w2p, 1024);
    bias_prep<<<16, 256>>>(b_ih1, b_hh1, b_ih2, b_hh2);
    gather_conv<<<(2048 * 1024) / 256, 256>>>(inputs, emb);
    mma_x1<<<dim3(128, 32), 128>>>();

    for (int t = 0; t < TT; t++) {
        const int p = t & 1;
        // cell 1: reads h1[p] bf16, writes h1[1-p] bf16 + h1f fp32, c1
        mma_cell<<<128, 512>>>(1, t,
            h1hi[p], h1lo[p], nullptr, nullptr, nullptr, nullptr,
            h1hi[1 - p], h1lo[1 - p], c1p, h1fp);
        attn_alpha<<<dim3(64, 7), 256>>>(img);
        attn_vatt<<<dim3(64, 4), 256>>>(img);
        // cell 2: reads va, h1[1-p], h2[p]; writes h2[1-p], c2, out[t]
        mma_cell<<<128, 512>>>(2, t,
            vahi, valo, h1hi[1 - p], h1lo[1 - p], h2hi[p], h2lo[p],
            h2hi[1 - p], h2lo[1 - p], c2p, out);
    }
}